// round 12
// baseline (speedup 1.0000x reference)
#include <cuda_runtime.h>
#include <math.h>

#define NBATCH  4
#define NPTS    8192
#define NC      24
#define NCELLS  (NC * NC * NC)          // 13824
#define SBLOCKS 32                       // search blocks per (dir,b): 8192/256
#define GROUPS  (2 * NBATCH)

// set 0 = rec, set 1 = data
__device__ float        g_box[2][NBATCH][6];          // minx,miny,minz,maxx,maxy,maxz
__device__ int          g_hist[2][NBATCH][NCELLS];
__device__ int          g_start[2][NBATCH][NCELLS];
__device__ int          g_cursor[2][NBATCH][NCELLS];
__device__ float4       g_sorted[2][NBATCH][NPTS];
__device__ float        g_part[GROUPS][SBLOCKS];
__device__ float        g_gsum[2][NBATCH];
__device__ unsigned int g_c1[GROUPS];    // zero-init; reset by final finisher
__device__ unsigned int g_c2;            // zero-init; reset by final finisher

// ---------- K_A: zero histograms + per-(set,batch) bounding box ----------
__global__ void k_box(const float* __restrict__ rec, const float* __restrict__ data) {
    const int bi  = blockIdx.x;          // 0..7
    const int s   = bi >> 2;
    const int b   = bi & 3;
    const int tid = threadIdx.x;         // 256 threads

    // zero this (s,b)'s histogram
    int* hist = g_hist[s][b];
    for (int i = tid; i < NCELLS; i += 256) hist[i] = 0;

    const float* src = (s == 0 ? rec : data) + (size_t)b * NPTS * 3;
    float mn[3] = { 3.4e38f,  3.4e38f,  3.4e38f};
    float mx[3] = {-3.4e38f, -3.4e38f, -3.4e38f};
    for (int i = tid; i < NPTS; i += 256) {
        #pragma unroll
        for (int a = 0; a < 3; ++a) {
            float v = src[3 * i + a];
            mn[a] = fminf(mn[a], v);
            mx[a] = fmaxf(mx[a], v);
        }
    }
    __shared__ float sm[6][256];
    #pragma unroll
    for (int a = 0; a < 3; ++a) { sm[a][tid] = mn[a]; sm[a + 3][tid] = mx[a]; }
    __syncthreads();
    for (int st = 128; st > 0; st >>= 1) {
        if (tid < st) {
            #pragma unroll
            for (int a = 0; a < 3; ++a) {
                sm[a][tid]     = fminf(sm[a][tid],     sm[a][tid + st]);
                sm[a + 3][tid] = fmaxf(sm[a + 3][tid], sm[a + 3][tid + st]);
            }
        }
        __syncthreads();
    }
    if (tid < 6) g_box[s][b][tid] = sm[tid][0];
}

__device__ __forceinline__ int cell_of(float v, float bmin, float invh) {
    int i = (int)((v - bmin) * invh);
    return min(max(i, 0), NC - 1);
}

// ---------- K_B: histogram ----------
__global__ void k_hist(const float* __restrict__ rec, const float* __restrict__ data) {
    const int s = blockIdx.z, b = blockIdx.y;
    const int i = blockIdx.x * 256 + threadIdx.x;
    const float* src = (s == 0 ? rec : data) + ((size_t)b * NPTS + i) * 3;
    const float* bx = g_box[s][b];
    float ivx = NC / (bx[3] - bx[0] + 1e-6f);
    float ivy = NC / (bx[4] - bx[1] + 1e-6f);
    float ivz = NC / (bx[5] - bx[2] + 1e-6f);
    int cx = cell_of(src[0], bx[0], ivx);
    int cy = cell_of(src[1], bx[1], ivy);
    int cz = cell_of(src[2], bx[2], ivz);
    atomicAdd(&g_hist[s][b][(cz * NC + cy) * NC + cx], 1);
}

// ---------- K_C: exclusive scan -> starts + cursors ----------
#define PERT 14   // 1024 * 14 >= 13824
__global__ __launch_bounds__(1024) void k_scan() {
    const int bi = blockIdx.x;           // 0..7
    const int s  = bi >> 2;
    const int b  = bi & 3;
    const int tid = threadIdx.x;
    __shared__ int ssum[1024];

    const int* hist = g_hist[s][b];
    int base = tid * PERT;
    int loc[PERT];
    int tot = 0;
    #pragma unroll
    for (int i = 0; i < PERT; ++i) {
        int c = base + i;
        loc[i] = tot;
        tot += (c < NCELLS) ? hist[c] : 0;
    }
    ssum[tid] = tot;
    __syncthreads();
    for (int off = 1; off < 1024; off <<= 1) {
        int v = (tid >= off) ? ssum[tid - off] : 0;
        __syncthreads();
        ssum[tid] += v;
        __syncthreads();
    }
    int exbase = ssum[tid] - tot;
    #pragma unroll
    for (int i = 0; i < PERT; ++i) {
        int c = base + i;
        if (c < NCELLS) {
            int st = exbase + loc[i];
            g_start[s][b][c]  = st;
            g_cursor[s][b][c] = st;
        }
    }
}

// ---------- K_D: scatter points into cell-sorted order ----------
__global__ void k_scatter(const float* __restrict__ rec, const float* __restrict__ data) {
    const int s = blockIdx.z, b = blockIdx.y;
    const int i = blockIdx.x * 256 + threadIdx.x;
    const float* src = (s == 0 ? rec : data) + ((size_t)b * NPTS + i) * 3;
    const float* bx = g_box[s][b];
    float ivx = NC / (bx[3] - bx[0] + 1e-6f);
    float ivy = NC / (bx[4] - bx[1] + 1e-6f);
    float ivz = NC / (bx[5] - bx[2] + 1e-6f);
    float x = src[0], y = src[1], z = src[2];
    int cx = cell_of(x, bx[0], ivx);
    int cy = cell_of(y, bx[1], ivy);
    int cz = cell_of(z, bx[2], ivz);
    int pos = atomicAdd(&g_cursor[s][b][(cz * NC + cy) * NC + cx], 1);
    g_sorted[s][b][pos] = make_float4(x, y, z, 0.0f);
}

// ---------- K_E: exact NN via expanding Chebyshev rings + reduce ----------
__global__ __launch_bounds__(256) void k_search(const float* __restrict__ rec,
                                                const float* __restrict__ data,
                                                float* __restrict__ out) {
    const int tid  = threadIdx.x;
    const int dir  = blockIdx.z;         // 0: queries=rec, db=data ; 1: reverse
    const int b    = blockIdx.y;
    const int qi   = blockIdx.x * 256 + tid;
    const int ds   = 1 - dir;            // db set index
    const int group = dir * NBATCH + b;

    const float* qsrc = (dir == 0 ? rec : data) + ((size_t)b * NPTS + qi) * 3;
    float qx = qsrc[0], qy = qsrc[1], qz = qsrc[2];

    const float* bx = g_box[ds][b];
    float rx = bx[3] - bx[0] + 1e-6f;
    float ry = bx[4] - bx[1] + 1e-6f;
    float rz = bx[5] - bx[2] + 1e-6f;
    float ivx = NC / rx, ivy = NC / ry, ivz = NC / rz;
    float hmin = fminf(rx, fminf(ry, rz)) * (1.0f / NC);

    int cx = cell_of(qx, bx[0], ivx);
    int cy = cell_of(qy, bx[1], ivy);
    int cz = cell_of(qz, bx[2], ivz);

    const float4* __restrict__ pts = g_sorted[ds][b];
    const int*    __restrict__ hst = g_hist[ds][b];
    const int*    __restrict__ stt = g_start[ds][b];

    float best = 3.4e38f;

    for (int k = 0; k < NC; ++k) {
        if (k >= 1) {
            float lb = (k - 1) * hmin;
            if (best <= lb * lb) break;
        }
        int zlo = max(cz - k, 0), zhi = min(cz + k, NC - 1);
        int ylo = max(cy - k, 0), yhi = min(cy + k, NC - 1);
        for (int z = zlo; z <= zhi; ++z) {
            int adz = abs(z - cz);
            for (int y = ylo; y <= yhi; ++y) {
                int ady = abs(y - cy);
                int xa, xb_;
                if (adz < k && ady < k) {        // interior: only x = cx±k
                    xa = cx - k; xb_ = cx + k;
                } else {
                    xa = max(cx - k, 0); xb_ = min(cx + k, NC - 1);
                }
                for (int x = xa; x <= xb_; x += (adz < k && ady < k) ? (2 * k > 0 ? 2 * k : 1) : 1) {
                    if (x < 0 || x >= NC) continue;
                    int cell = (z * NC + y) * NC + x;
                    int s0 = stt[cell];
                    int n  = hst[cell];
                    for (int i = 0; i < n; ++i) {
                        float4 p = pts[s0 + i];
                        float dx = p.x - qx, dy = p.y - qy, dz = p.z - qz;
                        float d = fmaf(dx, dx, fmaf(dy, dy, dz * dz));
                        best = fminf(best, d);
                    }
                }
            }
        }
    }

    // ---- block tree-sum of per-query min distances ----
    __shared__ float red[256];
    __shared__ int   s_flag;
    red[tid] = fmaxf(best, 0.0f);
    __syncthreads();
    for (int st = 128; st > 0; st >>= 1) {
        if (tid < st) red[tid] += red[tid + st];
        __syncthreads();
    }
    if (tid == 0) {
        g_part[group][blockIdx.x] = red[0];
        __threadfence();
        unsigned int t = atomicAdd(&g_c1[group], 1u);
        s_flag = (t == SBLOCKS - 1) ? 1 : 0;
    }
    __syncthreads();

    if (s_flag && tid == 0) {
        __threadfence();
        float s = 0.0f;
        #pragma unroll
        for (int c = 0; c < SBLOCKS; ++c) s += g_part[group][c];
        g_gsum[dir][b] = s;
        __threadfence();
        unsigned int t2 = atomicAdd(&g_c2, 1u);
        if (t2 == GROUPS - 1) {
            __threadfence();
            float total = 0.0f;
            #pragma unroll
            for (int bb = 0; bb < NBATCH; ++bb) {
                float mr = g_gsum[0][bb] * (1.0f / NPTS);
                float md = g_gsum[1][bb] * (1.0f / NPTS);
                total += fmaxf(mr, md);
            }
            out[0] = total * (1.0f / NBATCH);
            #pragma unroll
            for (int gg = 0; gg < GROUPS; ++gg) g_c1[gg] = 0u;
            g_c2 = 0u;
        }
    }
}

extern "C" void kernel_launch(void* const* d_in, const int* in_sizes, int n_in,
                              void* d_out, int out_size) {
    const float* rec  = (const float*)d_in[0];   // (B, N, 3) fp32
    const float* data = (const float*)d_in[1];   // (B, M, 3) fp32
    float* out = (float*)d_out;

    dim3 pgrid(NPTS / 256, NBATCH, 2);           // 32 x 4 x 2

    k_box    <<<8, 256>>>(rec, data);
    k_hist   <<<pgrid, 256>>>(rec, data);
    k_scan   <<<8, 1024>>>();
    k_scatter<<<pgrid, 256>>>(rec, data);
    k_search <<<pgrid, 256>>>(rec, data, out);
}

// round 13
// speedup vs baseline: 2.5784x; 2.5784x over previous
#include <cuda_runtime.h>

#define NBATCH 4
#define NPTS   8192
#define NC     16
#define NCELLS (NC * NC * NC)     // 4096
#define PTH    512                // prep threads
#define STH    128                // search threads
#define SBLK   (NPTS / STH)       // 64 search blocks per (dir,b)
#define GROUPS 8

__device__ float        g_box[2][NBATCH][6];        // min xyz, max xyz
__device__ int          g_start[2][NBATCH][NCELLS + 1];
__device__ float4       g_sorted[2][NBATCH][NPTS];  // cell-sorted, w = ||p||^2
__device__ double       g_part[GROUPS][SBLK];
__device__ double       g_gsum[GROUPS];
__device__ unsigned int g_c1[GROUPS];               // zero-init; reset by finisher
__device__ unsigned int g_c2;                       // zero-init; reset by finisher

__device__ __forceinline__ int cidx(float v, float bmin, float inv) {
    int i = (int)((v - bmin) * inv);
    return min(max(i, 0), NC - 1);
}

// ---- one fused prep: bbox -> histogram -> scan -> scatter (per set,batch) ----
__global__ __launch_bounds__(PTH) void k_prep(const float* __restrict__ rec,
                                              const float* __restrict__ data) {
    __shared__ float          sbox[6][PTH];       // 12 KB
    __shared__ int            hist[NCELLS];       // 16 KB (becomes cursor)
    __shared__ unsigned short cells[NPTS];        // 16 KB
    __shared__ int            ssum[PTH];          // 2 KB

    const int s   = blockIdx.x >> 2;
    const int b   = blockIdx.x & 3;
    const int tid = threadIdx.x;
    const float* src = (s == 0 ? rec : data) + (size_t)b * NPTS * 3;

    // phase 1: bounding box
    float mn0 = 3.4e38f, mn1 = 3.4e38f, mn2 = 3.4e38f;
    float mx0 = -3.4e38f, mx1 = -3.4e38f, mx2 = -3.4e38f;
    for (int i = tid; i < NPTS; i += PTH) {
        float x = src[3 * i], y = src[3 * i + 1], z = src[3 * i + 2];
        mn0 = fminf(mn0, x); mx0 = fmaxf(mx0, x);
        mn1 = fminf(mn1, y); mx1 = fmaxf(mx1, y);
        mn2 = fminf(mn2, z); mx2 = fmaxf(mx2, z);
    }
    sbox[0][tid] = mn0; sbox[1][tid] = mn1; sbox[2][tid] = mn2;
    sbox[3][tid] = mx0; sbox[4][tid] = mx1; sbox[5][tid] = mx2;
    __syncthreads();
    for (int st = PTH / 2; st > 0; st >>= 1) {
        if (tid < st) {
            #pragma unroll
            for (int a = 0; a < 3; ++a) {
                sbox[a][tid]     = fminf(sbox[a][tid],     sbox[a][tid + st]);
                sbox[a + 3][tid] = fmaxf(sbox[a + 3][tid], sbox[a + 3][tid + st]);
            }
        }
        __syncthreads();
    }
    if (tid < 6) g_box[s][b][tid] = sbox[tid][0];
    const float bx0 = sbox[0][0], by0 = sbox[1][0], bz0 = sbox[2][0];
    const float ivx = NC / (sbox[3][0] - bx0 + 1e-6f);
    const float ivy = NC / (sbox[4][0] - by0 + 1e-6f);
    const float ivz = NC / (sbox[5][0] - bz0 + 1e-6f);
    __syncthreads();

    // phase 2: histogram (smem)
    for (int i = tid; i < NCELLS; i += PTH) hist[i] = 0;
    __syncthreads();
    for (int i = tid; i < NPTS; i += PTH) {
        float x = src[3 * i], y = src[3 * i + 1], z = src[3 * i + 2];
        int c = (cidx(z, bz0, ivz) * NC + cidx(y, by0, ivy)) * NC + cidx(x, bx0, ivx);
        cells[i] = (unsigned short)c;
        atomicAdd(&hist[c], 1);
    }
    __syncthreads();

    // phase 3: exclusive scan (8 cells/thread + block scan)
    const int base = tid * 8;
    int loc[8], tot = 0;
    #pragma unroll
    for (int j = 0; j < 8; ++j) { loc[j] = tot; tot += hist[base + j]; }
    ssum[tid] = tot;
    __syncthreads();
    for (int off = 1; off < PTH; off <<= 1) {
        int v = (tid >= off) ? ssum[tid - off] : 0;
        __syncthreads();
        ssum[tid] += v;
        __syncthreads();
    }
    const int ex = ssum[tid] - tot;
    #pragma unroll
    for (int j = 0; j < 8; ++j) g_start[s][b][base + j] = ex + loc[j];
    if (tid == PTH - 1) g_start[s][b][NCELLS] = NPTS;
    __syncthreads();
    #pragma unroll
    for (int j = 0; j < 8; ++j) hist[base + j] = ex + loc[j];   // cursors
    __syncthreads();

    // phase 4: scatter (w = norm)
    for (int i = tid; i < NPTS; i += PTH) {
        int c = cells[i];
        int pos = atomicAdd(&hist[c], 1);
        float x = src[3 * i], y = src[3 * i + 1], z = src[3 * i + 2];
        g_sorted[s][b][pos] = make_float4(x, y, z, fmaf(x, x, fmaf(y, y, z * z)));
    }
}

// ---- exact NN over sorted grid: 27-cell fast path + rare ring expansion ----
__global__ __launch_bounds__(STH) void k_search(float* __restrict__ out) {
    const int tid = threadIdx.x;
    const int dir = blockIdx.z;          // 0: rec->data, 1: data->rec
    const int b   = blockIdx.y;
    const int qi  = blockIdx.x * STH + tid;
    const int qs  = dir;                 // query set (sorted order: sum-invariant)
    const int ds  = 1 - dir;             // database set
    const int group = dir * NBATCH + b;

    const float4 q = g_sorted[qs][b][qi];
    const float* bx = g_box[ds][b];
    const float rx = bx[3] - bx[0] + 1e-6f;
    const float ry = bx[4] - bx[1] + 1e-6f;
    const float rz = bx[5] - bx[2] + 1e-6f;
    const float ivx = NC / rx, ivy = NC / ry, ivz = NC / rz;
    const float hmin = fminf(rx, fminf(ry, rz)) * (1.0f / NC);

    const float A0 = -2.0f * q.x, A1 = -2.0f * q.y, A2 = -2.0f * q.z;
    const float q2 = q.w;
    const int cx = cidx(q.x, bx[0], ivx);
    const int cy = cidx(q.y, bx[1], ivy);
    const int cz = cidx(q.z, bx[2], ivz);

    const float4* __restrict__ pts = g_sorted[ds][b];
    const int*    __restrict__ stt = g_start[ds][b];

    float best0 = 3.4e38f, best1 = 3.4e38f;

    // fast path: 3x3x3 block as 9 contiguous runs
    {
        const int xlo = max(cx - 1, 0), xhi = min(cx + 1, NC - 1);
        const int ylo = max(cy - 1, 0), yhi = min(cy + 1, NC - 1);
        const int zlo = max(cz - 1, 0), zhi = min(cz + 1, NC - 1);
        for (int z = zlo; z <= zhi; ++z)
            for (int y = ylo; y <= yhi; ++y) {
                const int rb = (z * NC + y) * NC;
                int i = stt[rb + xlo];
                const int e = stt[rb + xhi + 1];
                for (; i + 1 < e; i += 2) {
                    float4 p  = pts[i];
                    float4 p2 = pts[i + 1];
                    float d0 = fmaf(A2, p.z,  fmaf(A1, p.y,  fmaf(A0, p.x,  q2))) + p.w;
                    float d1 = fmaf(A2, p2.z, fmaf(A1, p2.y, fmaf(A0, p2.x, q2))) + p2.w;
                    best0 = fminf(best0, d0);
                    best1 = fminf(best1, d1);
                }
                if (i < e) {
                    float4 p = pts[i];
                    best0 = fminf(best0,
                        fmaf(A2, p.z, fmaf(A1, p.y, fmaf(A0, p.x, q2))) + p.w);
                }
            }
    }
    float best = fminf(best0, best1);

    // rare path: expand Chebyshev blocks until bound proves optimality
    if (best > hmin * hmin) {
        for (int k = 2; k < NC; ++k) {
            const float lb = (k - 1) * hmin;
            if (best <= lb * lb) break;
            const int xlo = max(cx - k, 0), xhi = min(cx + k, NC - 1);
            const int ylo = max(cy - k, 0), yhi = min(cy + k, NC - 1);
            const int zlo = max(cz - k, 0), zhi = min(cz + k, NC - 1);
            for (int z = zlo; z <= zhi; ++z)
                for (int y = ylo; y <= yhi; ++y) {
                    const int rb = (z * NC + y) * NC;
                    int i = stt[rb + xlo];
                    const int e = stt[rb + xhi + 1];
                    for (; i < e; ++i) {
                        float4 p = pts[i];
                        float d = fmaf(A2, p.z, fmaf(A1, p.y, fmaf(A0, p.x, q2))) + p.w;
                        best0 = fminf(best0, d);
                    }
                }
            best = fminf(best0, best1);
        }
    }

    // ---- deterministic-enough reduction: double accumulation throughout ----
    __shared__ double red[STH];
    __shared__ int    s_flag;
    red[tid] = (double)fmaxf(best, 0.0f);
    __syncthreads();
    for (int st = STH / 2; st > 0; st >>= 1) {
        if (tid < st) red[tid] += red[tid + st];
        __syncthreads();
    }
    if (tid == 0) {
        g_part[group][blockIdx.x] = red[0];
        __threadfence();
        unsigned int t = atomicAdd(&g_c1[group], 1u);
        s_flag = (t == SBLK - 1) ? 1 : 0;
    }
    __syncthreads();

    if (s_flag && tid == 0) {
        __threadfence();
        double ssum = 0.0;
        #pragma unroll
        for (int c = 0; c < SBLK; ++c) ssum += g_part[group][c];
        g_gsum[group] = ssum;
        __threadfence();
        unsigned int t2 = atomicAdd(&g_c2, 1u);
        if (t2 == GROUPS - 1) {
            __threadfence();
            double total = 0.0;
            #pragma unroll
            for (int bb = 0; bb < NBATCH; ++bb) {
                double mr = g_gsum[0 * NBATCH + bb] * (1.0 / NPTS);
                double md = g_gsum[1 * NBATCH + bb] * (1.0 / NPTS);
                total += (mr > md) ? mr : md;
            }
            out[0] = (float)(total * (1.0 / NBATCH));
            #pragma unroll
            for (int gg = 0; gg < GROUPS; ++gg) g_c1[gg] = 0u;
            g_c2 = 0u;
        }
    }
}

extern "C" void kernel_launch(void* const* d_in, const int* in_sizes, int n_in,
                              void* d_out, int out_size) {
    const float* rec  = (const float*)d_in[0];   // (B, N, 3) fp32
    const float* data = (const float*)d_in[1];   // (B, M, 3) fp32
    float* out = (float*)d_out;

    k_prep<<<8, PTH>>>(rec, data);
    dim3 sgrid(SBLK, NBATCH, 2);                 // 64 x 4 x 2 = 512 blocks
    k_search<<<sgrid, STH>>>(out);
}